// round 16
// baseline (speedup 1.0000x reference)
#include <cuda_runtime.h>
#include <cuda_bf16.h>
#include <cstdint>

#define NROWS 8192
#define KDIM  128
#define GAMMA_F 0.005f   // 1/(2*10^2)

#define TILE 128
#define THREADS 256
#define CTILES 2

// SMEM: padded bf16 tiles, row stride 272 bytes (128 bf16 = 256B + 16B pad)
#define ROW_BYTES 272
#define TILE_BYTES (TILE * ROW_BYTES)          // 34816
#define SMEM_A    0
#define SMEM_B0   TILE_BYTES                    // 34816
#define SMEM_B1   (2 * TILE_BYTES)              // 69632
#define SMEM_N1   (3 * TILE_BYTES)              // 104448
#define SMEM_N2_0 (SMEM_N1 + TILE * 4)          // 104960
#define SMEM_N2_1 (SMEM_N2_0 + TILE * 4)        // 105472
#define SMEM_TOTAL (SMEM_N2_1 + TILE * 4)       // 105984

__device__ float g_n1[NROWS];
__device__ float g_n2[NROWS];
__device__ __nv_bfloat16 g_x1b[NROWS * KDIM];   // 2 MB
__device__ __nv_bfloat16 g_x2b[NROWS * KDIM];   // 2 MB

static __device__ __forceinline__ uint32_t smem_u32(const void* p) {
    uint32_t a;
    asm("{ .reg .u64 t; cvta.to.shared.u64 t, %1; cvt.u32.u64 %0, t; }"
        : "=r"(a) : "l"(p));
    return a;
}

static __device__ __forceinline__ void cp_async16(uint32_t smem_addr, const void* gptr) {
    asm volatile("cp.async.cg.shared.global [%0], [%1], 16;"
                 :: "r"(smem_addr), "l"(gptr) : "memory");
}
static __device__ __forceinline__ void cp_commit() {
    asm volatile("cp.async.commit_group;" ::: "memory");
}
template <int N>
static __device__ __forceinline__ void cp_wait() {
    asm volatile("cp.async.wait_group %0;" :: "n"(N) : "memory");
}

static __device__ __forceinline__ void ldsm_x4(uint32_t& r0, uint32_t& r1,
                                               uint32_t& r2, uint32_t& r3,
                                               uint32_t addr) {
    asm volatile("ldmatrix.sync.aligned.m8n8.x4.shared.b16 {%0,%1,%2,%3}, [%4];"
                 : "=r"(r0), "=r"(r1), "=r"(r2), "=r"(r3) : "r"(addr));
}

static __device__ __forceinline__ void mma_16816(float* d,
                                                 const uint32_t* a,
                                                 uint32_t b0, uint32_t b1) {
    asm volatile(
        "mma.sync.aligned.m16n8k16.row.col.f32.bf16.bf16.f32 "
        "{%0,%1,%2,%3}, {%4,%5,%6,%7}, {%8,%9}, {%0,%1,%2,%3};"
        : "+f"(d[0]), "+f"(d[1]), "+f"(d[2]), "+f"(d[3])
        : "r"(a[0]), "r"(a[1]), "r"(a[2]), "r"(a[3]), "r"(b0), "r"(b1));
}

// Inverse column permutation applied at ldmatrix-address time (R13/R15-proven).
static __device__ __forceinline__ uint32_t perm4(uint32_t r) {
    return ((r & 8u) >> 2) | ((r & 4u) << 1) | ((r & 2u) << 1) | (r & 1u);
}

// ---------------- prep kernel: norms + fp32->bf16 conversion ----------------
__global__ void rbf_prep_kernel(const float* __restrict__ x1,
                                const float* __restrict__ x2)
{
    int warp = (blockIdx.x * blockDim.x + threadIdx.x) >> 5;
    int lane = threadIdx.x & 31;
    if (warp >= 2 * NROWS) return;
    const float* src = (warp < NROWS) ? x1 : x2;
    float* dstn = (warp < NROWS) ? g_n1 : g_n2;
    __nv_bfloat16* dstb = (warp < NROWS) ? g_x1b : g_x2b;
    int row = warp & (NROWS - 1);

    float4 v = reinterpret_cast<const float4*>(src + (size_t)row * KDIM)[lane];
    float s = v.x * v.x + v.y * v.y + v.z * v.z + v.w * v.w;
    #pragma unroll
    for (int m = 16; m > 0; m >>= 1)
        s += __shfl_xor_sync(0xFFFFFFFFu, s, m);
    if (lane == 0) dstn[row] = s;

    __nv_bfloat162 p0 = __floats2bfloat162_rn(v.x, v.y);
    __nv_bfloat162 p1 = __floats2bfloat162_rn(v.z, v.w);
    reinterpret_cast<uint2*>(dstb + (size_t)row * KDIM)[lane] =
        make_uint2(*reinterpret_cast<uint32_t*>(&p0), *reinterpret_cast<uint32_t*>(&p1));
}

// ---------------- main kernel: strip of 2 tiles, cp.async prefetch ----------
__global__ void __launch_bounds__(THREADS)
rbf_mma_kernel(const float* __restrict__ x1,
               const float* __restrict__ x2,
               float* __restrict__ out)
{
    extern __shared__ char smem[];
    uint32_t sbase = smem_u32(smem);
    int tid = threadIdx.x;
    int wid = tid >> 5;
    int lane = tid & 31;

    int rowBase = blockIdx.y * TILE;
    int colBase0 = blockIdx.x * CTILES * TILE;

    // ---- prologue: group0 = A + B0; group1 = B1; norms via regular LDG ----
    {
        const char* aG = reinterpret_cast<const char*>(g_x1b + (size_t)rowBase * KDIM);
        const char* b0G = reinterpret_cast<const char*>(g_x2b + (size_t)colBase0 * KDIM);
        const char* b1G = b0G + (size_t)TILE * KDIM * 2;
        #pragma unroll
        for (int it = 0; it < 8; ++it) {
            int idx = tid + it * THREADS;           // 0..2047
            int row = idx >> 4;
            int ch  = idx & 15;
            uint32_t off = (uint32_t)row * ROW_BYTES + (uint32_t)ch * 16;
            cp_async16(sbase + SMEM_A + off, aG + (size_t)idx * 16);
            cp_async16(sbase + SMEM_B0 + off, b0G + (size_t)idx * 16);
        }
        cp_commit();                                 // group: A + B0
        #pragma unroll
        for (int it = 0; it < 8; ++it) {
            int idx = tid + it * THREADS;
            int row = idx >> 4;
            int ch  = idx & 15;
            uint32_t off = (uint32_t)row * ROW_BYTES + (uint32_t)ch * 16;
            cp_async16(sbase + SMEM_B1 + off, b1G + (size_t)idx * 16);
        }
        cp_commit();                                 // group: B1

        if (tid < TILE) {
            reinterpret_cast<float*>(smem + SMEM_N1)[tid] = g_n1[rowBase + tid];
        } else {
            int t = tid - TILE;
            reinterpret_cast<float*>(smem + SMEM_N2_0)[t] = g_n2[colBase0 + t];
            reinterpret_cast<float*>(smem + SMEM_N2_1)[t] = g_n2[colBase0 + TILE + t];
        }
        cp_wait<1>();                                // A + B0 complete
    }
    __syncthreads();

    int mw = wid >> 2;       // 0..1
    int nw = wid & 3;        // 0..3
    uint32_t lrow  = lane & 15;
    uint32_t lrowB = perm4(lrow);
    uint32_t lhalf = (lane >> 4) * 16;

    #pragma unroll
    for (int ct = 0; ct < CTILES; ++ct) {
        int colBase = colBase0 + ct * TILE;
        uint32_t bufB = ct ? SMEM_B1 : SMEM_B0;
        const float* sn2 = reinterpret_cast<const float*>(
            smem + (ct ? SMEM_N2_1 : SMEM_N2_0));

        if (ct == 1) {
            cp_wait<0>();    // B1 complete (streamed under tile 0)
            __syncthreads();
        }

        float acc[4][4][4];
        #pragma unroll
        for (int mi = 0; mi < 4; ++mi)
            #pragma unroll
            for (int ni = 0; ni < 4; ++ni)
                #pragma unroll
                for (int r = 0; r < 4; ++r) acc[mi][ni][r] = 0.0f;

        uint32_t bAddr0 = sbase + bufB + ((uint32_t)(nw * 32) + lrowB) * ROW_BYTES + lhalf;
        uint32_t bAddr1 = bAddr0 + 16 * ROW_BYTES;

        #pragma unroll
        for (int ks = 0; ks < 8; ++ks) {
            uint32_t koff = (uint32_t)ks * 32;

            uint32_t af[4][4];
            #pragma unroll
            for (int mi = 0; mi < 4; ++mi) {
                uint32_t row = (uint32_t)(mw * 64 + mi * 16) + lrow;
                ldsm_x4(af[mi][0], af[mi][1], af[mi][2], af[mi][3],
                        sbase + SMEM_A + row * ROW_BYTES + lhalf + koff);
            }
            uint32_t bf[2][4];
            ldsm_x4(bf[0][0], bf[0][1], bf[0][2], bf[0][3], bAddr0 + koff);
            ldsm_x4(bf[1][0], bf[1][1], bf[1][2], bf[1][3], bAddr1 + koff);

            #pragma unroll
            for (int mi = 0; mi < 4; ++mi) {
                #pragma unroll
                for (int ni = 0; ni < 4; ++ni) {
                    int nj = ni >> 1, sub = ni & 1;
                    mma_16816(acc[mi][ni], af[mi], bf[nj][sub], bf[nj][sub + 2]);
                }
            }
        }

        // ---- epilogue (R15): contiguous float4 stores, no shuffles ----
        {
            const float* sn1 = reinterpret_cast<const float*>(smem + SMEM_N1);
            int qr = lane >> 2;
            int qi = lane & 3;

            float4 n2v[2];
            #pragma unroll
            for (int p = 0; p < 2; ++p)
                n2v[p] = *reinterpret_cast<const float4*>(sn2 + nw * 32 + p * 16 + qi * 4);

            #pragma unroll
            for (int mi = 0; mi < 4; ++mi) {
                int row0 = mw * 64 + mi * 16 + qr;
                float n1a = sn1[row0];
                float n1b = sn1[row0 + 8];
                #pragma unroll
                for (int p = 0; p < 2; ++p) {
                    int col = nw * 32 + p * 16 + qi * 4;
                    const float* a = acc[mi][2 * p];
                    const float* b = acc[mi][2 * p + 1];
                    float4 oa, ob;
                    oa.x = __expf(-GAMMA_F * (n1a + n2v[p].x - 2.0f * a[0]));
                    oa.y = __expf(-GAMMA_F * (n1a + n2v[p].y - 2.0f * a[1]));
                    oa.z = __expf(-GAMMA_F * (n1a + n2v[p].z - 2.0f * b[0]));
                    oa.w = __expf(-GAMMA_F * (n1a + n2v[p].w - 2.0f * b[1]));
                    ob.x = __expf(-GAMMA_F * (n1b + n2v[p].x - 2.0f * a[2]));
                    ob.y = __expf(-GAMMA_F * (n1b + n2v[p].y - 2.0f * a[3]));
                    ob.z = __expf(-GAMMA_F * (n1b + n2v[p].z - 2.0f * b[2]));
                    ob.w = __expf(-GAMMA_F * (n1b + n2v[p].w - 2.0f * b[3]));
                    *reinterpret_cast<float4*>(
                        out + (size_t)(rowBase + row0) * NROWS + colBase + col) = oa;
                    *reinterpret_cast<float4*>(
                        out + (size_t)(rowBase + row0 + 8) * NROWS + colBase + col) = ob;
                }
            }
        }
    }
}

// ---------------- launch ----------------
extern "C" void kernel_launch(void* const* d_in, const int* in_sizes, int n_in,
                              void* d_out, int out_size)
{
    const float* x1 = (const float*)d_in[0];
    const float* x2 = (const float*)d_in[1];
    float* out = (float*)d_out;

    cudaFuncSetAttribute(rbf_mma_kernel,
                         cudaFuncAttributeMaxDynamicSharedMemorySize, SMEM_TOTAL);
    cudaFuncSetAttribute(rbf_mma_kernel,
                         cudaFuncAttributePreferredSharedMemoryCarveout, 100);

    rbf_prep_kernel<<<(2 * NROWS) / 8, 256>>>(x1, x2);

    dim3 grid(NROWS / (TILE * CTILES), NROWS / TILE);   // 32 x 64 = 2048
    rbf_mma_kernel<<<grid, THREADS, SMEM_TOTAL>>>(x1, x2, out);
}

// round 17
// speedup vs baseline: 1.0641x; 1.0641x over previous
#include <cuda_runtime.h>
#include <cuda_bf16.h>
#include <cstdint>

#define NROWS 8192
#define KDIM  128
#define GAMMA_F 0.005f   // 1/(2*10^2)

#define TILE 128
#define THREADS 256

// SMEM: padded bf16 tiles, row stride 272 bytes (128 bf16 = 256B + 16B pad)
#define ROW_BYTES 272
#define TILE_BYTES (TILE * ROW_BYTES)          // 34816
#define SMEM_A  0
#define SMEM_B  TILE_BYTES                      // 34816
#define SMEM_N1 (2 * TILE_BYTES)                // 69632
#define SMEM_N2 (SMEM_N1 + TILE * 4)            // 70144
#define SMEM_TOTAL (SMEM_N2 + TILE * 4)         // 70656

__device__ float g_n1[NROWS];
__device__ float g_n2[NROWS];
__device__ __nv_bfloat16 g_x1b[NROWS * KDIM];   // 2 MB
__device__ __nv_bfloat16 g_x2b[NROWS * KDIM];   // 2 MB

static __device__ __forceinline__ uint32_t smem_u32(const void* p) {
    uint32_t a;
    asm("{ .reg .u64 t; cvta.to.shared.u64 t, %1; cvt.u32.u64 %0, t; }"
        : "=r"(a) : "l"(p));
    return a;
}

static __device__ __forceinline__ void cp_async16(uint32_t smem_addr, const void* gptr) {
    asm volatile("cp.async.cg.shared.global [%0], [%1], 16;"
                 :: "r"(smem_addr), "l"(gptr) : "memory");
}
static __device__ __forceinline__ void cp_async_commit_wait() {
    asm volatile("cp.async.commit_group;" ::: "memory");
    asm volatile("cp.async.wait_group 0;" ::: "memory");
}

static __device__ __forceinline__ void ldsm_x4(uint32_t& r0, uint32_t& r1,
                                               uint32_t& r2, uint32_t& r3,
                                               uint32_t addr) {
    asm volatile("ldmatrix.sync.aligned.m8n8.x4.shared.b16 {%0,%1,%2,%3}, [%4];"
                 : "=r"(r0), "=r"(r1), "=r"(r2), "=r"(r3) : "r"(addr));
}

static __device__ __forceinline__ void mma_16816(float* d,
                                                 const uint32_t* a,
                                                 uint32_t b0, uint32_t b1) {
    asm volatile(
        "mma.sync.aligned.m16n8k16.row.col.f32.bf16.bf16.f32 "
        "{%0,%1,%2,%3}, {%4,%5,%6,%7}, {%8,%9}, {%0,%1,%2,%3};"
        : "+f"(d[0]), "+f"(d[1]), "+f"(d[2]), "+f"(d[3])
        : "r"(a[0]), "r"(a[1]), "r"(a[2]), "r"(a[3]), "r"(b0), "r"(b1));
}

// Inverse column permutation applied at ldmatrix-address time (R13/R15-proven).
static __device__ __forceinline__ uint32_t perm4(uint32_t r) {
    return ((r & 8u) >> 2) | ((r & 4u) << 1) | ((r & 2u) << 1) | (r & 1u);
}

// ---------------- prep kernel: norms + fp32->bf16 conversion ----------------
__global__ void rbf_prep_kernel(const float* __restrict__ x1,
                                const float* __restrict__ x2)
{
    int warp = (blockIdx.x * blockDim.x + threadIdx.x) >> 5;
    int lane = threadIdx.x & 31;
    if (warp >= 2 * NROWS) return;
    const float* src = (warp < NROWS) ? x1 : x2;
    float* dstn = (warp < NROWS) ? g_n1 : g_n2;
    __nv_bfloat16* dstb = (warp < NROWS) ? g_x1b : g_x2b;
    int row = warp & (NROWS - 1);

    float4 v = reinterpret_cast<const float4*>(src + (size_t)row * KDIM)[lane];
    float s = v.x * v.x + v.y * v.y + v.z * v.z + v.w * v.w;
    #pragma unroll
    for (int m = 16; m > 0; m >>= 1)
        s += __shfl_xor_sync(0xFFFFFFFFu, s, m);
    if (lane == 0) dstn[row] = s;

    __nv_bfloat162 p0 = __floats2bfloat162_rn(v.x, v.y);
    __nv_bfloat162 p1 = __floats2bfloat162_rn(v.z, v.w);
    reinterpret_cast<uint2*>(dstb + (size_t)row * KDIM)[lane] =
        make_uint2(*reinterpret_cast<uint32_t*>(&p0), *reinterpret_cast<uint32_t*>(&p1));
}

// ---------------- main kernel: cp.async + permuted-B + pipelined frags ------
__global__ void __launch_bounds__(THREADS, 2)
rbf_mma_kernel(const float* __restrict__ x1,
               const float* __restrict__ x2,
               float* __restrict__ out)
{
    extern __shared__ char smem[];
    uint32_t sbase = smem_u32(smem);
    int tid = threadIdx.x;
    int wid = tid >> 5;
    int lane = tid & 31;

    int rowBase = blockIdx.y * TILE;
    int colBase = blockIdx.x * TILE;

    // ---- async tile loads: bf16 GMEM -> padded SMEM (R14/R15 exact) ----
    {
        const char* aG = reinterpret_cast<const char*>(g_x1b + (size_t)rowBase * KDIM);
        const char* bG = reinterpret_cast<const char*>(g_x2b + (size_t)colBase * KDIM);
        #pragma unroll
        for (int it = 0; it < 8; ++it) {
            int idx = tid + it * THREADS;           // 0..2047
            int row = idx >> 4;
            int ch  = idx & 15;
            uint32_t off = (uint32_t)row * ROW_BYTES + (uint32_t)ch * 16;
            cp_async16(sbase + SMEM_A + off, aG + (size_t)idx * 16);
            cp_async16(sbase + SMEM_B + off, bG + (size_t)idx * 16);
        }
        if (tid < TILE) {
            reinterpret_cast<float*>(smem + SMEM_N1)[tid] = g_n1[rowBase + tid];
        } else {
            reinterpret_cast<float*>(smem + SMEM_N2)[tid - TILE] = g_n2[colBase + (tid - TILE)];
        }
        cp_async_commit_wait();
    }
    __syncthreads();

    // ---- mma mainloop: warp grid 2(M) x 4(N); double-buffered fragments ----
    int mw = wid >> 2;       // 0..1
    int nw = wid & 3;        // 0..3

    float acc[4][4][4];      // [mi][tile][reg]
    #pragma unroll
    for (int mi = 0; mi < 4; ++mi)
        #pragma unroll
        for (int ni = 0; ni < 4; ++ni)
            #pragma unroll
            for (int r = 0; r < 4; ++r) acc[mi][ni][r] = 0.0f;

    uint32_t lrow  = lane & 15;
    uint32_t lrowB = perm4(lrow);        // one-time permuted B lane row
    uint32_t lhalf = (lane >> 4) * 16;   // byte offset of k-half

    uint32_t aAddr  = sbase + SMEM_A + ((uint32_t)(mw * 64) + lrow) * ROW_BYTES + lhalf;
    uint32_t bAddr0 = sbase + SMEM_B + ((uint32_t)(nw * 32) + lrowB) * ROW_BYTES + lhalf;
    uint32_t bAddr1 = bAddr0 + 16 * ROW_BYTES;

    uint32_t af[2][4][4];    // [buf][mi][reg]
    uint32_t bf[2][2][4];    // [buf][nj][reg]

    // preload ks=0 fragments
    #pragma unroll
    for (int mi = 0; mi < 4; ++mi)
        ldsm_x4(af[0][mi][0], af[0][mi][1], af[0][mi][2], af[0][mi][3],
                aAddr + (uint32_t)(mi * 16) * ROW_BYTES);
    ldsm_x4(bf[0][0][0], bf[0][0][1], bf[0][0][2], bf[0][0][3], bAddr0);
    ldsm_x4(bf[0][1][0], bf[0][1][1], bf[0][1][2], bf[0][1][3], bAddr1);

    #pragma unroll
    for (int ks = 0; ks < 8; ++ks) {
        int cur = ks & 1;
        int nxt = cur ^ 1;

        // prefetch next K-step's fragments BEFORE consuming current ones
        if (ks < 7) {
            uint32_t koff = (uint32_t)(ks + 1) * 32;
            #pragma unroll
            for (int mi = 0; mi < 4; ++mi)
                ldsm_x4(af[nxt][mi][0], af[nxt][mi][1], af[nxt][mi][2], af[nxt][mi][3],
                        aAddr + (uint32_t)(mi * 16) * ROW_BYTES + koff);
            ldsm_x4(bf[nxt][0][0], bf[nxt][0][1], bf[nxt][0][2], bf[nxt][0][3],
                    bAddr0 + koff);
            ldsm_x4(bf[nxt][1][0], bf[nxt][1][1], bf[nxt][1][2], bf[nxt][1][3],
                    bAddr1 + koff);
        }

        #pragma unroll
        for (int mi = 0; mi < 4; ++mi) {
            #pragma unroll
            for (int ni = 0; ni < 4; ++ni) {
                int nj = ni >> 1, sub = ni & 1;
                mma_16816(acc[mi][ni], af[cur][mi], bf[cur][nj][sub], bf[cur][nj][sub + 2]);
            }
        }
    }

    // ---- epilogue (R15): contiguous float4 stores, no shuffles ----
    {
        const float* sn1 = reinterpret_cast<const float*>(smem + SMEM_N1);
        const float* sn2 = reinterpret_cast<const float*>(smem + SMEM_N2);
        int qr = lane >> 2;          // 0..7
        int qi = lane & 3;           // 0..3

        float4 n2v[2];
        #pragma unroll
        for (int p = 0; p < 2; ++p)
            n2v[p] = *reinterpret_cast<const float4*>(sn2 + nw * 32 + p * 16 + qi * 4);

        #pragma unroll
        for (int mi = 0; mi < 4; ++mi) {
            int row0 = mw * 64 + mi * 16 + qr;       // rows row0, row0+8
            float n1a = sn1[row0];
            float n1b = sn1[row0 + 8];
            #pragma unroll
            for (int p = 0; p < 2; ++p) {
                int col = nw * 32 + p * 16 + qi * 4;
                const float* a = acc[mi][2 * p];
                const float* b = acc[mi][2 * p + 1];
                float4 oa, ob;
                oa.x = __expf(-GAMMA_F * (n1a + n2v[p].x - 2.0f * a[0]));
                oa.y = __expf(-GAMMA_F * (n1a + n2v[p].y - 2.0f * a[1]));
                oa.z = __expf(-GAMMA_F * (n1a + n2v[p].z - 2.0f * b[0]));
                oa.w = __expf(-GAMMA_F * (n1a + n2v[p].w - 2.0f * b[1]));
                ob.x = __expf(-GAMMA_F * (n1b + n2v[p].x - 2.0f * a[2]));
                ob.y = __expf(-GAMMA_F * (n1b + n2v[p].y - 2.0f * a[3]));
                ob.z = __expf(-GAMMA_F * (n1b + n2v[p].z - 2.0f * b[2]));
                ob.w = __expf(-GAMMA_F * (n1b + n2v[p].w - 2.0f * b[3]));
                *reinterpret_cast<float4*>(
                    out + (size_t)(rowBase + row0) * NROWS + colBase + col) = oa;
                *reinterpret_cast<float4*>(
                    out + (size_t)(rowBase + row0 + 8) * NROWS + colBase + col) = ob;
            }
        }
    }
}

// ---------------- launch ----------------
extern "C" void kernel_launch(void* const* d_in, const int* in_sizes, int n_in,
                              void* d_out, int out_size)
{
    const float* x1 = (const float*)d_in[0];
    const float* x2 = (const float*)d_in[1];
    float* out = (float*)d_out;

    cudaFuncSetAttribute(rbf_mma_kernel,
                         cudaFuncAttributeMaxDynamicSharedMemorySize, SMEM_TOTAL);
    cudaFuncSetAttribute(rbf_mma_kernel,
                         cudaFuncAttributePreferredSharedMemoryCarveout, 100);

    rbf_prep_kernel<<<(2 * NROWS) / 8, 256>>>(x1, x2);

    dim3 grid(NROWS / TILE, NROWS / TILE);   // 64 x 64
    rbf_mma_kernel<<<grid, THREADS, SMEM_TOTAL>>>(x1, x2, out);
}